// round 13
// baseline (speedup 1.0000x reference)
#include <cuda_runtime.h>

// Problem constants (B=1, H=32, Q=1024, S=4096, D=128)
#define SEQ      4096
#define ROWS     32768      // B*H*Q rows of attn_weights
#define START    4
#define HEAVY    409        // int(4096*0.1)
#define RSTART   3687       // 4096 - min(409,512)
#define NCAND    3683       // RSTART - START
#define NKEEP    822        // 4 + 409 + 409
#define HEADS    32
#define NBLK     148        // one exact wave
#define NTHR     1024
#define NSEL     256        // selection warps (0-7)
#define NGAT     768        // gather warps (8-31)
#define NFIX     413        // START + recent rows (selection-independent)
#define TOTAL_F  (2*HEADS*NFIX*32)    // fixed-gather float4 = 845824
#define TOTAL_H  (2*HEADS*HEAVY*32)   // heavy-gather float4 = 837632
#define SETCAP   256        // max prefix-tie set (expected ~1-5)

// Named barrier for the 256 selection threads only.
#define BAR_SEL() asm volatile("bar.sync 1, %0;" :: "n"(NSEL) : "memory")

// Scratch. g_sums is atomically accumulated so it MUST be zero at entry:
// in k_tail, the last block to FINISH LOADING g_sums re-zeroes it at its
// end (arrive counter, no waiting). g_done reset by that same block.
__device__ double g_sums[SEQ];
__device__ int    g_done;

// ================= Kernel 1: column sums (512 MB PURE READ stream) =========
// 148 blocks, contiguous row range each (measured ~82us @ ~83% DRAM).
// Thread t owns columns [4t,4t+4) via float4; 8 front-batched LDG.128
// (MLP=8); __ldcs (no reuse). fp32 over 32 rows flushed into fp64 keeps the
// mean accurate to ~1e-8 rel (top-k boundary gap ~1e-5); fp64 atomicAdd
// ordering noise ~1e-13 — selection identical to reference (rel_err 0.0).
__global__ void __launch_bounds__(NTHR, 1) k_colsum(const float* __restrict__ w) {
    const int t = threadIdx.x;
    const int b = blockIdx.x;
    const int r0 = (int)((long long)ROWS * b / NBLK);
    const int r1 = (int)((long long)ROWS * (b + 1) / NBLK);
    const float4* __restrict__ w4 = (const float4*)w + t;
    double a0 = 0, a1 = 0, a2 = 0, a3 = 0;
    float  c0 = 0, c1 = 0, c2 = 0, c3 = 0;
    int row = r0, grp = 0;
    for (; row + 8 <= r1; row += 8) {
        float4 v[8];
        #pragma unroll
        for (int k = 0; k < 8; k++)
            v[k] = __ldcs(&w4[(size_t)(row + k) * 1024]);
        float s0x = (v[0].x + v[1].x) + (v[2].x + v[3].x);
        float s1x = (v[4].x + v[5].x) + (v[6].x + v[7].x);
        float s0y = (v[0].y + v[1].y) + (v[2].y + v[3].y);
        float s1y = (v[4].y + v[5].y) + (v[6].y + v[7].y);
        float s0z = (v[0].z + v[1].z) + (v[2].z + v[3].z);
        float s1z = (v[4].z + v[5].z) + (v[6].z + v[7].z);
        float s0w = (v[0].w + v[1].w) + (v[2].w + v[3].w);
        float s1w = (v[4].w + v[5].w) + (v[6].w + v[7].w);
        c0 += s0x + s1x;  c1 += s0y + s1y;
        c2 += s0z + s1z;  c3 += s0w + s1w;
        if (++grp == 4) {                 // flush every 32 rows
            a0 += c0; a1 += c1; a2 += c2; a3 += c3;
            c0 = c1 = c2 = c3 = 0.f; grp = 0;
        }
    }
    for (; row < r1; row++) {
        float4 v = __ldcs(&w4[(size_t)row * 1024]);
        c0 += v.x; c1 += v.y; c2 += v.z; c3 += v.w;
    }
    a0 += c0; a1 += c1; a2 += c2; a3 += c3;
    int s = 4 * t;
    atomicAdd(&g_sums[s + 0], a0);
    atomicAdd(&g_sums[s + 1], a1);
    atomicAdd(&g_sums[s + 2], a2);
    atomicAdd(&g_sums[s + 3], a3);
}

// ==== Kernel 2: warp-specialized select || fixed-gather -> heavy gather ====
// Warps 0-7 : load sums, 3-level radix-select (u64 bit-order isomorphic for
//             positive doubles), exact tie subset (reference comparator:
//             value desc, index asc == jax.lax.top_k), build heavy list.
// Warps 8-31: fixed gather (sinks + recent, analytic addressing) in parallel.
// Join at __syncthreads(), then all warps do the heavy gather.
__global__ void __launch_bounds__(NTHR, 1)
k_tail(const float4* __restrict__ keys,
       const float4* __restrict__ vals,
       float4* __restrict__ out) {
    __shared__ unsigned long long sj[NCAND];
    __shared__ int  hist[2048];
    __shared__ int  s_keep[HEAVY];             // heavy source idxs (sorted)
    __shared__ int  warpsum[8];
    __shared__ int  s_bin, s_R, s_setcnt, s_zero;
    __shared__ int  s_setidx[SETCAP];
    __shared__ unsigned char s_take[SETCAP];

    const int t = threadIdx.x;
    const int b = blockIdx.x;
    const int lane = t & 31, w = t >> 5;

    if (t < NSEL) {
        // =================== SELECTION PIPELINE (256 threads) ==============
        for (int k = t; k < NCAND; k += NSEL)
            sj[k] = __double_as_longlong(__ldcg(&g_sums[START + k]));
        if (t == 0) s_setcnt = 0;
        BAR_SEL();
        if (t == 0) {
            __threadfence();
            s_zero = (atomicAdd(&g_done, 1) == NBLK - 1) ? 1 : 0;
        }

        // ---- 3-level radix select (11 bits per level) ---------------------
        unsigned long long pfx = 0;
        int R = HEAVY;
        #pragma unroll
        for (int lvl = 0; lvl < 3; lvl++) {
            const int shift = 53 - 11 * lvl;   // 53, 42, 31
            for (int i = t; i < 2048; i += NSEL) hist[i] = 0;
            BAR_SEL();
            for (int k = t; k < NCAND; k += NSEL) {
                unsigned long long key = sj[k];
                if (lvl == 0 || (key >> (shift + 11)) == pfx)
                    atomicAdd(&hist[(int)((key >> shift) & 0x7FF)], 1);
            }
            BAR_SEL();
            // thread handles 8 consecutive reversed bins
            const int rb = t * 8;
            int vv[8], pair = 0;
            #pragma unroll
            for (int j = 0; j < 8; j++) {
                vv[j] = hist[2047 - (rb + j)];
                pair += vv[j];
            }
            int v = pair;
            #pragma unroll
            for (int o = 1; o < 32; o <<= 1) {
                int n = __shfl_up_sync(0xFFFFFFFFu, v, o);
                if (lane >= o) v += n;
            }
            if (lane == 31) warpsum[w] = v;
            BAR_SEL();
            if (w == 0 && lane < 8) {
                int s = warpsum[lane];
                #pragma unroll
                for (int o = 1; o < 8; o <<= 1) {
                    int n = __shfl_up_sync(0x000000FFu, s, o);
                    if (lane >= o) s += n;
                }
                warpsum[lane] = s;
            }
            BAR_SEL();
            int T = v - pair + (w > 0 ? warpsum[w - 1] : 0);
            #pragma unroll
            for (int j = 0; j < 8; j++) {
                T += vv[j];
                if (T - vv[j] < R && R <= T) {
                    s_bin = 2047 - (rb + j);
                    s_R = R - (T - vv[j]);
                }
            }
            BAR_SEL();
            pfx = (pfx << 11) | (unsigned long long)s_bin;
            R = s_R;
            BAR_SEL();
        }

        // ---- exact tie subset at the 33-bit threshold prefix --------------
        for (int k = t; k < NCAND; k += NSEL) {
            if ((sj[k] >> 31) == pfx) {
                int p = atomicAdd(&s_setcnt, 1);
                if (p < SETCAP) s_setidx[p] = k;
            }
        }
        BAR_SEL();
        const int setcnt = min(s_setcnt, SETCAP);
        if (w == 0) {
            for (int m = lane; m < setcnt; m += 32) {
                int im = s_setidx[m];
                unsigned long long km = sj[im];
                int rk = 0;
                for (int j = 0; j < setcnt; j++) {
                    int ij = s_setidx[j];
                    unsigned long long kj = sj[ij];
                    rk += (kj > km || (kj == km && ij < im)) ? 1 : 0;
                }
                s_take[m] = (rk < R) ? 1 : 0;
            }
        }
        BAR_SEL();

        // ---- build heavy keep list (15 candidates per thread) -------------
        {
            int f[15], loc = 0;
            const int base = 15 * t;
            #pragma unroll
            for (int k = 0; k < 15; k++) {
                int c = base + k;
                int fl = 0;
                if (c < NCAND) {
                    unsigned long long hk = sj[c] >> 31;
                    if (hk > pfx) fl = 1;
                    else if (hk == pfx) {
                        for (int m = 0; m < setcnt; m++)
                            if (s_setidx[m] == c) { fl = s_take[m]; break; }
                    }
                }
                f[k] = fl; loc += fl;
            }
            int v = loc;
            #pragma unroll
            for (int o = 1; o < 32; o <<= 1) {
                int n = __shfl_up_sync(0xFFFFFFFFu, v, o);
                if (lane >= o) v += n;
            }
            if (lane == 31) warpsum[w] = v;
            BAR_SEL();
            if (w == 0 && lane < 8) {
                int s = warpsum[lane];
                #pragma unroll
                for (int o = 1; o < 8; o <<= 1) {
                    int n = __shfl_up_sync(0x000000FFu, s, o);
                    if (lane >= o) s += n;
                }
                warpsum[lane] = s;
            }
            BAR_SEL();
            int pos = v - loc + (w > 0 ? warpsum[w - 1] : 0);
            #pragma unroll
            for (int k = 0; k < 15; k++) {
                if (f[k]) { s_keep[pos] = START + base + k; pos++; }
            }
        }
    } else {
        // =================== FIXED GATHER (768 threads) ====================
        // sinks + recent window: selection-independent, analytic addressing.
        const int gt = t - NSEL;
        const int stride = NBLK * NGAT;        // 113664
        int v = b * NGAT + gt;
        for (; v + 3 * stride < TOTAL_F; v += 4 * stride) {
            float4 d[4];
            size_t oidx[4];
            #pragma unroll
            for (int k = 0; k < 4; k++) {
                int vv  = v + k * stride;
                int d4  = vv & 31;
                int row = vv >> 5;
                int tensor = row / (HEADS * NFIX);
                int rem = row - tensor * (HEADS * NFIX);
                int h   = rem / NFIX;
                int p   = rem - h * NFIX;              // 0..412
                int r   = (p < START) ? p : p + HEAVY; // output row (keep order)
                int s   = (p < START) ? p : (RSTART + p - START);
                const float4* __restrict__ src = tensor ? vals : keys;
                d[k] = __ldcs(&src[(((size_t)h * SEQ + s) << 5) + d4]);
                oidx[k] = (((size_t)(tensor * HEADS + h) * NKEEP + r) << 5) + d4;
            }
            #pragma unroll
            for (int k = 0; k < 4; k++) out[oidx[k]] = d[k];
        }
        for (; v < TOTAL_F; v += stride) {
            int d4  = v & 31;
            int row = v >> 5;
            int tensor = row / (HEADS * NFIX);
            int rem = row - tensor * (HEADS * NFIX);
            int h   = rem / NFIX;
            int p   = rem - h * NFIX;
            int r   = (p < START) ? p : p + HEAVY;
            int s   = (p < START) ? p : (RSTART + p - START);
            const float4* __restrict__ src = tensor ? vals : keys;
            out[(((size_t)(tensor * HEADS + h) * NKEEP + r) << 5) + d4] =
                __ldcs(&src[(((size_t)h * SEQ + s) << 5) + d4]);
        }
    }

    __syncthreads();   // join: s_keep ready, fixed gather issued

    // ---- Phase D: heavy gather (all 1024 threads, unroll-4) ---------------
    {
        const int stride = NBLK * NTHR;         // 151552
        int v = b * NTHR + t;
        for (; v + 3 * stride < TOTAL_H; v += 4 * stride) {
            float4 d[4];
            size_t oidx[4];
            #pragma unroll
            for (int k = 0; k < 4; k++) {
                int vv  = v + k * stride;
                int d4  = vv & 31;
                int row = vv >> 5;
                int tensor = row / (HEADS * HEAVY);
                int rem = row - tensor * (HEADS * HEAVY);
                int h   = rem / HEAVY;
                int q   = rem - h * HEAVY;             // heavy slot 0..408
                int s   = s_keep[q];
                const float4* __restrict__ src = tensor ? vals : keys;
                d[k] = __ldcs(&src[(((size_t)h * SEQ + s) << 5) + d4]);
                oidx[k] = (((size_t)(tensor * HEADS + h) * NKEEP + (START + q)) << 5) + d4;
            }
            #pragma unroll
            for (int k = 0; k < 4; k++) out[oidx[k]] = d[k];
        }
        for (; v < TOTAL_H; v += stride) {
            int d4  = v & 31;
            int row = v >> 5;
            int tensor = row / (HEADS * HEAVY);
            int rem = row - tensor * (HEADS * HEAVY);
            int h   = rem / HEAVY;
            int q   = rem - h * HEAVY;
            int s   = s_keep[q];
            const float4* __restrict__ src = tensor ? vals : keys;
            out[(((size_t)(tensor * HEADS + h) * NKEEP + (START + q)) << 5) + d4] =
                __ldcs(&src[(((size_t)h * SEQ + s) << 5) + d4]);
        }
    }

    // ---- epilogue: designated block re-zeroes g_sums for next call --------
    __syncthreads();
    if (s_zero) {
        for (int i = t; i < SEQ; i += NTHR) g_sums[i] = 0.0;
        if (t == 0) g_done = 0;
    }
}

extern "C" void kernel_launch(void* const* d_in, const int* in_sizes, int n_in,
                              void* d_out, int out_size) {
    const float* keys = (const float*)d_in[0];   // (1,32,4096,128)
    const float* vals = (const float*)d_in[1];   // (1,32,4096,128)
    const float* attn = (const float*)d_in[2];   // (1,32,1024,4096)
    float* out = (float*)d_out;                  // 2*32*822*128 f32

    k_colsum<<<NBLK, NTHR>>>(attn);
    k_tail<<<NBLK, NTHR>>>((const float4*)keys, (const float4*)vals,
                           (float4*)out);
}